// round 15
// baseline (speedup 1.0000x reference)
#include <cuda_runtime.h>
#include <math.h>

#define NB   4
#define NP   19248
#define NC   81
#define NM   32
#define TOPK 100
#define CAND 108       // candidate margin over TOPK
#define KEEP 15
#define PH   138
#define PW   138
#define IH   550
#define IW   550
#define NPX  (IH * IW)  // 302500, %4 == 0
#define EPSF 1e-6f
#define NBINS 4096
#define TI   8
#define NT   13        // ceil(100/8)
#define NTP  91        // NT*(NT+1)/2
#define PXB2 128       // pixels per k_final block
#define FCH2 149       // ceil(138*138 / 128)

// ---------------- scratch (static device memory) ----------------
__device__ float    g_key[NB * NP];
__device__ float    g_sconf[NB][TOPK];
__device__ float    g_sloc[NB][TOPK][4];
__device__ float    g_smask[NB][TOPK][NM];
__device__ float    g_ioumax[NB][TOPK];     // atomicMax via positive-float int bits
__device__ float4   g_kpr[NB][KEEP];        // cx, cy, ix, iy
__device__ float    g_kcf[NB][KEEP];
__device__ float4   g_kmask4[NB][KEEP][8];
__device__ float    g_final[NB][PH * PW];
__device__ double   g_acc;
__device__ unsigned g_done;
__device__ unsigned g_ioudone;

// ---------------- fast math on FMA pipe ----------------
__device__ __forceinline__ float fexp(float x) {
    x = fminf(fmaxf(x, -87.0f), 88.0f);
    float t = x * 1.4426950408889634f;
    float fi = rintf(t);
    float f = t - fi;
    float p =            1.5403530e-4f;
    p = fmaf(p, f, 1.3333558e-3f);
    p = fmaf(p, f, 9.6181291e-3f);
    p = fmaf(p, f, 5.5504109e-2f);
    p = fmaf(p, f, 2.4022651e-1f);
    p = fmaf(p, f, 6.9314718e-1f);
    p = fmaf(p, f, 1.0f);
    int ei = (int)fi;
    return p * __int_as_float((ei + 127) << 23);
}
__device__ __forceinline__ float frcp(float y) {
    float r = __int_as_float(0x7EF311C3 - __float_as_int(y));
    r = r * (2.0f - y * r);
    r = r * (2.0f - y * r);
    r = r * (2.0f - y * r);
    return r;
}

// ---------------- K1: ordering key per anchor (monotone in conf1) ----------------
__global__ void k_score(const float* __restrict__ conf) {
    int warp = (blockIdx.x * blockDim.x + threadIdx.x) >> 5;
    int lane = threadIdx.x & 31;
    if (warp >= NB * NP) return;
    const float* row = conf + (size_t)warp * NC;
    float v0 = row[lane];
    float v1 = (lane + 32 < NC) ? row[lane + 32] : -INFINITY;
    float v2 = (lane + 64 < NC) ? row[lane + 64] : -INFINITY;
    float m = fmaxf(v0, fmaxf(v1, v2));
    #pragma unroll
    for (int o = 16; o; o >>= 1) m = fmaxf(m, __shfl_xor_sync(0xffffffffu, m, o));
    float s = fexp(v0 - m);
    if (lane + 32 < NC) s += fexp(v1 - m);
    if (lane + 64 < NC) s += fexp(v2 - m);
    #pragma unroll
    for (int o = 16; o; o >>= 1) s += __shfl_xor_sync(0xffffffffu, s, o);
    float c1 = __shfl_sync(0xffffffffu, v0, 1);
    if (lane == 0) g_key[warp] = (c1 - m) * 1.4426950408889634f - __log2f(s);
}

__device__ __forceinline__ unsigned key_bucket(float k) {
    unsigned u = __float_as_uint(k);
    u = (u & 0x80000000u) ? ~u : (u | 0x80000000u);
    unsigned b = u >> 19;
    return b > (NBINS - 1) ? (NBINS - 1) : b;
}

// ---------------- K2: one block per batch: hist -> threshold -> compact ->
//                   exact conf1 recompute -> stable sort -> gather top-100 ----------------
__global__ void k_select(const float* __restrict__ conf,
                         const float* __restrict__ loc,
                         const float* __restrict__ mask) {
    __shared__ unsigned s_hist[NBINS];
    __shared__ unsigned s_chunk[32];
    __shared__ int s_cnt, s_thr;
    __shared__ float s_val[1024];
    __shared__ int   s_idx[1024];
    int b = blockIdx.x, t = threadIdx.x;
    int lane = t & 31, wp = t >> 5;

    for (int i = t; i < NBINS; i += 1024) s_hist[i] = 0;
    if (t == 0) s_cnt = 0;
    __syncthreads();
    cudaGridDependencySynchronize();       // need g_key from k_score
    for (int i = t; i < NP; i += 1024)
        atomicAdd(&s_hist[key_bucket(g_key[b * NP + i])], 1u);
    __syncthreads();
    unsigned cs = s_hist[wp * 128 + lane] + s_hist[wp * 128 + lane + 32] +
                  s_hist[wp * 128 + lane + 64] + s_hist[wp * 128 + lane + 96];
    #pragma unroll
    for (int o = 16; o; o >>= 1) cs += __shfl_xor_sync(0xffffffffu, cs, o);
    if (lane == 0) s_chunk[wp] = cs;
    __syncthreads();
    if (t < 32) {
        unsigned suff = s_chunk[t];
        #pragma unroll
        for (int o = 1; o < 32; o <<= 1) {
            unsigned x = __shfl_down_sync(0xffffffffu, suff, o);
            if (t + o < 32) suff += x;
        }
        unsigned sn = __shfl_down_sync(0xffffffffu, suff, 1);
        if (t == 31) sn = 0;
        if (suff >= CAND && sn < CAND) {
            unsigned acc = sn;
            int thr = t * 128;
            for (int bin = t * 128 + 127; bin >= t * 128; --bin) {
                acc += s_hist[bin];
                if (acc >= CAND) { thr = bin; break; }
            }
            s_thr = thr;
        }
    }
    __syncthreads();
    int thr = s_thr;
    for (int i = t; i < NP; i += 1024) {
        if ((int)key_bucket(g_key[b * NP + i]) >= thr) {
            int pos = atomicAdd(&s_cnt, 1);
            if (pos < 1024) s_idx[pos] = i;
        }
    }
    __syncthreads();
    int cnt = s_cnt; if (cnt > 1024) cnt = 1024;
    for (int c = wp; c < cnt; c += 32) {
        const float* row = conf + (size_t)(b * NP + s_idx[c]) * NC;
        float v0 = row[lane];
        float v1 = (lane + 32 < NC) ? row[lane + 32] : -INFINITY;
        float v2 = (lane + 64 < NC) ? row[lane + 64] : -INFINITY;
        float m = fmaxf(v0, fmaxf(v1, v2));
        #pragma unroll
        for (int o = 16; o; o >>= 1) m = fmaxf(m, __shfl_xor_sync(0xffffffffu, m, o));
        float s = expf(v0 - m);
        if (lane + 32 < NC) s += expf(v1 - m);
        if (lane + 64 < NC) s += expf(v2 - m);
        #pragma unroll
        for (int o = 16; o; o >>= 1) s += __shfl_xor_sync(0xffffffffu, s, o);
        float c1 = __shfl_sync(0xffffffffu, v0, 1);
        if (lane == 0) s_val[c] = expf(c1 - m) / s;
    }
    __syncthreads();
    int S = 1; while (S < cnt) S <<= 1;
    if (t >= cnt && t < S) { s_val[t] = -INFINITY; s_idx[t] = 0x7fffffff; }
    __syncthreads();
    for (int k2 = 2; k2 <= S; k2 <<= 1) {
        for (int j = k2 >> 1; j; j >>= 1) {
            if (t < S) {
                int p = t ^ j;
                if (p > t) {
                    float av = s_val[t], bv = s_val[p];
                    int   ai = s_idx[t], bi = s_idx[p];
                    bool tfirst = (av > bv) || (av == bv && ai < bi);
                    bool desc = ((t & k2) == 0);
                    if (desc ? !tfirst : tfirst) {
                        s_val[t] = bv; s_val[p] = av; s_idx[t] = bi; s_idx[p] = ai;
                    }
                }
            }
            __syncthreads();
        }
    }
    if (t < TOPK) {
        int idx = s_idx[t];
        g_sconf[b][t] = s_val[t];
        *(float4*)&g_sloc[b][t][0] = *(const float4*)(loc + (size_t)(b * NP + idx) * 4);
        const float4* mp = (const float4*)(mask + (size_t)(b * NP + idx) * NM);
        float4* dst = (float4*)&g_smask[b][t][0];
        #pragma unroll
        for (int q = 0; q < 8; q++) dst[q] = mp[q];
        g_ioumax[b][t] = 0.f;
    }
    if (b == 0 && t == 0) { g_acc = 0.0; g_done = 0u; g_ioudone = 0u; }
}

// ---------------- K3: fused gaussian generation + tiled pairwise IoU;
//                   last-arriving block computes keep-15 for all batches ----------------
__global__ void k_iou() {
    __shared__ float shB[TI][1024];
    __shared__ float shS[TI];
    __shared__ int   s_keep[NB][KEEP];
    __shared__ int   s_last;
    int b = blockIdx.x / NTP;
    int q = blockIdx.x % NTP;
    int ti = 0;
    while (q >= NT - ti) { q -= NT - ti; ti++; }
    int tj = ti + q;
    int t = threadIdx.x, wp = t >> 5, l = t & 31;
    float xs = (l + 0.5f) * (1.f / 32.f);
    cudaGridDependencySynchronize();       // need g_sloc/g_ioumax from k_select

    int i = ti * TI + wp;
    int ic = min(i, TOPK - 1);
    float cx = g_sloc[b][ic][0], cy = g_sloc[b][ic][1];
    float sx = fabsf(g_sloc[b][ic][2]) * 0.5f + 0.001f;
    float sy = fabsf(g_sloc[b][ic][3]) * 0.5f + 0.001f;
    float ix = 0.5f * frcp(sx * sx), iy = 0.5f * frcp(sy * sy);
    float dxq = (xs - cx); dxq = dxq * dxq * ix;
    float a[32]; float Si = 0.f;
    #pragma unroll
    for (int r = 0; r < 32; r++) {
        float dy = (r + 0.5f) * (1.f / 32.f) - cy;
        float g = fexp(-fmaf(dy * dy, iy, dxq));
        a[r] = g; Si += g;
    }
    #pragma unroll
    for (int o = 16; o; o >>= 1) Si += __shfl_xor_sync(0xffffffffu, Si, o);

    int j = tj * TI + wp;
    int jc = min(j, TOPK - 1);
    float bx = g_sloc[b][jc][0], by = g_sloc[b][jc][1];
    float bsx = fabsf(g_sloc[b][jc][2]) * 0.5f + 0.001f;
    float bsy = fabsf(g_sloc[b][jc][3]) * 0.5f + 0.001f;
    float bix = 0.5f * frcp(bsx * bsx), biy = 0.5f * frcp(bsy * bsy);
    float bdxq = (xs - bx); bdxq = bdxq * bdxq * bix;
    float Sj = 0.f;
    #pragma unroll
    for (int r = 0; r < 32; r++) {
        float dy = (r + 0.5f) * (1.f / 32.f) - by;
        float g = fexp(-fmaf(dy * dy, biy, bdxq));
        shB[wp][r * 32 + l] = g; Sj += g;
    }
    #pragma unroll
    for (int o = 16; o; o >>= 1) Sj += __shfl_xor_sync(0xffffffffu, Sj, o);
    if (l == 0) shS[wp] = Sj;
    __syncthreads();

    for (int jr = 0; jr < TI; jr++) {
        int jj = tj * TI + jr;
        if (i < jj && jj < TOPK) {
            float D = 0.f;
            #pragma unroll
            for (int r = 0; r < 32; r++) D += fabsf(a[r] - shB[jr][r * 32 + l]);
            #pragma unroll
            for (int o = 16; o; o >>= 1) D += __shfl_xor_sync(0xffffffffu, D, o);
            if (l == 0) {
                float S = Si + shS[jr];
                float iou = (S - D) * frcp(S + D);     // in (0,1): int-bit atomicMax valid
                atomicMax((int*)&g_ioumax[b][jj], __float_as_int(iou));
            }
        }
    }

    // ---- tail: last-arriving block computes keep-15 + compact params for all batches ----
    __syncthreads();
    if (t == 0) {
        __threadfence();
        unsigned d = atomicAdd(&g_ioudone, 1u);
        s_last = (d == NB * NTP - 1u) ? 1 : 0;
    }
    __syncthreads();
    if (!s_last) return;
    if (wp < NB) {
        int b2 = wp;
        float v[4]; int id[4];
        #pragma unroll
        for (int r = 0; r < 4; r++) {
            int ixp = l + 32 * r; id[r] = ixp;
            v[r] = (ixp < TOPK) ? __int_as_float(__ldcg((const int*)&g_ioumax[b2][ixp])) : INFINITY;
        }
        int mykeep = -1;
        for (int it = 0; it < KEEP; ++it) {
            float bv = INFINITY; int bi = 0x7fffffff;
            #pragma unroll
            for (int r = 0; r < 4; r++)
                if (v[r] < bv || (v[r] == bv && id[r] < bi)) { bv = v[r]; bi = id[r]; }
            #pragma unroll
            for (int o = 16; o; o >>= 1) {
                float ov = __shfl_xor_sync(0xffffffffu, bv, o);
                int   oi = __shfl_xor_sync(0xffffffffu, bi, o);
                if (ov < bv || (ov == bv && oi < bi)) { bv = ov; bi = oi; }
            }
            if (l == it) mykeep = bi;
            #pragma unroll
            for (int r = 0; r < 4; r++) if (id[r] == bi) v[r] = INFINITY;
        }
        if (l < KEEP) {
            int k = mykeep;
            s_keep[b2][l] = k;
            float ksx = fabsf(g_sloc[b2][k][2]) * 0.5f + 0.001f;
            float ksy = fabsf(g_sloc[b2][k][3]) * 0.5f + 0.001f;
            float4 pr;
            pr.x = g_sloc[b2][k][0];
            pr.y = g_sloc[b2][k][1];
            pr.z = 0.5f * frcp(ksx * ksx);
            pr.w = 0.5f * frcp(ksy * ksy);
            g_kpr[b2][l] = pr;
            g_kcf[b2][l] = g_sconf[b2][k];
        }
        __syncwarp();
        for (int idx = l; idx < KEEP * 8; idx += 32) {
            int kk = idx >> 3, q8 = idx & 7;
            g_kmask4[b2][kk][q8] = *(const float4*)&g_smask[b2][s_keep[b2][kk]][q8 * 4];
        }
    }
}

// ---------------- K4: final_conf; prologue-free; 128 px/block x 2-way keep-split ----------------
__global__ void __launch_bounds__(256) k_final(const float* __restrict__ proto) {
    __shared__ float4 skm4[KEEP][8];
    __shared__ float4 spr[KEEP];
    __shared__ float  scf[KEEP];
    __shared__ float  s_d1[PXB2], s_n1[PXB2];
    int bx = blockIdx.x;
    int b = bx / FCH2, chunk = bx % FCH2;
    int t = threadIdx.x;
    int half = t >> 7, p = t & 127;
    int px = chunk * PXB2 + p;
    bool valid = (px < PH * PW);

    // proto is a kernel INPUT: load before the PDL sync to overlap k_iou tail
    float4 pv[8];
    if (valid) {
        const float4* pp = (const float4*)(proto + ((size_t)b * (PH * PW) + px) * NM);
        #pragma unroll
        for (int i2 = 0; i2 < 8; i2++) pv[i2] = pp[i2];
    }
    cudaGridDependencySynchronize();       // need g_kpr/g_kcf/g_kmask4 from k_iou tail

    if (t < KEEP * 8) skm4[t >> 3][t & 7] = g_kmask4[b][t >> 3][t & 7];
    else if (t >= 128 && t < 128 + KEEP) { spr[t - 128] = g_kpr[b][t - 128]; scf[t - 128] = g_kcf[b][t - 128]; }
    __syncthreads();

    float denom = 0.f, num = 0.f;
    if (valid) {
        int h = px / PW, w = px % PW;
        float xs = (w + 0.5f) * (1.f / 138.f), ys = (h + 0.5f) * (1.f / 138.f);
        int kbeg = half ? 8 : 0;
        int kcnt = half ? (KEEP - 8) : 8;
        #pragma unroll
        for (int k = 0; k < 8; k++) {
            if (k >= kcnt) break;
            int kk = kbeg + k;
            float4 m0 = skm4[kk][0], m1 = skm4[kk][1], m2 = skm4[kk][2], m3 = skm4[kk][3];
            float d0 = 0.f, d1 = 0.f, d2 = 0.f, d3 = 0.f;
            d0 = fmaf(pv[0].x, m0.x, d0); d0 = fmaf(pv[0].y, m0.y, d0);
            d0 = fmaf(pv[0].z, m0.z, d0); d0 = fmaf(pv[0].w, m0.w, d0);
            d1 = fmaf(pv[1].x, m1.x, d1); d1 = fmaf(pv[1].y, m1.y, d1);
            d1 = fmaf(pv[1].z, m1.z, d1); d1 = fmaf(pv[1].w, m1.w, d1);
            d2 = fmaf(pv[2].x, m2.x, d2); d2 = fmaf(pv[2].y, m2.y, d2);
            d2 = fmaf(pv[2].z, m2.z, d2); d2 = fmaf(pv[2].w, m2.w, d2);
            d3 = fmaf(pv[3].x, m3.x, d3); d3 = fmaf(pv[3].y, m3.y, d3);
            d3 = fmaf(pv[3].z, m3.z, d3); d3 = fmaf(pv[3].w, m3.w, d3);
            m0 = skm4[kk][4]; m1 = skm4[kk][5]; m2 = skm4[kk][6]; m3 = skm4[kk][7];
            d0 = fmaf(pv[4].x, m0.x, d0); d0 = fmaf(pv[4].y, m0.y, d0);
            d0 = fmaf(pv[4].z, m0.z, d0); d0 = fmaf(pv[4].w, m0.w, d0);
            d1 = fmaf(pv[5].x, m1.x, d1); d1 = fmaf(pv[5].y, m1.y, d1);
            d1 = fmaf(pv[5].z, m1.z, d1); d1 = fmaf(pv[5].w, m1.w, d1);
            d2 = fmaf(pv[6].x, m2.x, d2); d2 = fmaf(pv[6].y, m2.y, d2);
            d2 = fmaf(pv[6].z, m2.z, d2); d2 = fmaf(pv[6].w, m2.w, d2);
            d3 = fmaf(pv[7].x, m3.x, d3); d3 = fmaf(pv[7].y, m3.y, d3);
            d3 = fmaf(pv[7].z, m3.z, d3); d3 = fmaf(pv[7].w, m3.w, d3);
            float dot = (d0 + d1) + (d2 + d3);
            float4 pr = spr[kk];
            float dx = xs - pr.x, dy = ys - pr.y;
            float sig = frcp(1.f + fexp(-dot));
            float ug = fexp(-(dx * dx * pr.z + dy * dy * pr.w));
            float aa = sig * ug * scf[kk];
            denom += aa; num = fmaf(aa, aa, num);
        }
    }
    if (half) { s_d1[p] = denom; s_n1[p] = num; }
    __syncthreads();
    if (!half && valid) {
        denom += s_d1[p]; num += s_n1[p];
        float f = 1.f - num * frcp(denom + EPSF);
        if (isnan(f)) f = 0.f;
        g_final[b][px] = f;
    }
}

// ---------------- K5: fused bilinear resize + weighted variance; 4 px/thread ----------------
__global__ void k_loss(const float* __restrict__ orig, float* __restrict__ out) {
    __shared__ float red[8];
    int i4 = blockIdx.x * 256 + threadIdx.x;
    bool act = (i4 < NPX / 4);
    int p0 = i4 * 4;
    float4 ov[3][NB];
    if (act) {
        #pragma unroll
        for (int c = 0; c < 3; c++)
            #pragma unroll
            for (int b = 0; b < NB; b++)
                ov[c][b] = *(const float4*)(orig + (size_t)(b * 3 + c) * NPX + p0);
    }
    cudaGridDependencySynchronize();       // need g_final
    float local = 0.f;
    if (act) {
        #pragma unroll
        for (int e = 0; e < 4; e++) {
            int p = p0 + e;
            int hh = p / IW, ww = p % IW;
            float fy = (hh + 0.5f) * (138.f / 550.f) - 0.5f;
            float fx = (ww + 0.5f) * (138.f / 550.f) - 0.5f;
            float y0f = floorf(fy), x0f = floorf(fx);
            float wy = fy - y0f, wx = fx - x0f;
            int y0 = (int)y0f, x0 = (int)x0f;
            int y0c = min(max(y0, 0), PH - 1), y1c = min(max(y0 + 1, 0), PH - 1);
            int x0c = min(max(x0, 0), PW - 1), x1c = min(max(x0 + 1, 0), PW - 1);
            float rb[NB]; float total = 0.f;
            #pragma unroll
            for (int b = 0; b < NB; b++) {
                const float* F = g_final[b];
                float v00 = F[y0c * PW + x0c], v01 = F[y0c * PW + x1c];
                float v10 = F[y1c * PW + x0c], v11 = F[y1c * PW + x1c];
                float v = (1.f - wy) * ((1.f - wx) * v00 + wx * v01)
                        +        wy  * ((1.f - wx) * v10 + wx * v11);
                rb[b] = v; total += v;
            }
            float acc = 0.f;
            #pragma unroll
            for (int c = 0; c < 3; c++) {
                float ob[NB]; float wm = 0.f;
                #pragma unroll
                for (int b = 0; b < NB; b++) {
                    float4 qv = ov[c][b];
                    ob[b] = (e == 0) ? qv.x : (e == 1) ? qv.y : (e == 2) ? qv.z : qv.w;
                    wm = fmaf(ob[b], rb[b], wm);
                }
                #pragma unroll
                for (int b = 0; b < NB; b++) {
                    float d = ob[b] - wm;
                    acc = fmaf(d * d, rb[b], acc);
                }
            }
            local += acc * frcp(total + EPSF);
        }
    }
    int t = threadIdx.x;
    float s = local;
    #pragma unroll
    for (int o = 16; o; o >>= 1) s += __shfl_xor_sync(0xffffffffu, s, o);
    if ((t & 31) == 0) red[t >> 5] = s;
    __syncthreads();
    if (t == 0) {
        float bs = 0.f;
        #pragma unroll
        for (int q2 = 0; q2 < 8; q2++) bs += red[q2];
        atomicAdd(&g_acc, (double)bs);
        __threadfence();
        unsigned v = atomicAdd(&g_done, 1u);
        if (v == gridDim.x - 1)
            out[0] = (float)(*((volatile double*)&g_acc) * 0.01);
    }
}

// ---------------- launch: 5 graph nodes chained via PDL ----------------
template <typename K, typename... Args>
static inline void launch_pdl(K kernel, dim3 grid, dim3 block, Args... args) {
    cudaLaunchConfig_t cfg = {};
    cfg.gridDim = grid;
    cfg.blockDim = block;
    cfg.dynamicSmemBytes = 0;
    cfg.stream = 0;
    cudaLaunchAttribute attr[1];
    attr[0].id = cudaLaunchAttributeProgrammaticStreamSerialization;
    attr[0].val.programmaticStreamSerializationAllowed = 1;
    cfg.attrs = attr;
    cfg.numAttrs = 1;
    cudaLaunchKernelEx(&cfg, kernel, args...);
}

extern "C" void kernel_launch(void* const* d_in, const int* in_sizes, int n_in,
                              void* d_out, int out_size) {
    const float* orig  = (const float*)d_in[0];
    const float* loc   = (const float*)d_in[1];
    const float* conf  = (const float*)d_in[2];
    const float* mask  = (const float*)d_in[3];
    const float* proto = (const float*)d_in[4];
    float* out = (float*)d_out;

    k_score<<<(NB * NP + 7) / 8, 256>>>(conf);
    launch_pdl(k_select, dim3(NB), dim3(1024), conf, loc, mask);
    launch_pdl(k_iou, dim3(NB * NTP), dim3(256));
    launch_pdl(k_final, dim3(NB * FCH2), dim3(256), proto);
    launch_pdl(k_loss, dim3((NPX / 4 + 255) / 256), dim3(256), orig, out);
}

// round 16
// speedup vs baseline: 1.1465x; 1.1465x over previous
#include <cuda_runtime.h>
#include <math.h>

#define NB   4
#define NP   19248
#define NC   81
#define NM   32
#define TOPK 100
#define CAND 108       // candidate margin over TOPK
#define KEEP 15
#define PH   138
#define PW   138
#define IH   550
#define IW   550
#define NPX  (IH * IW)  // 302500, %4 == 0
#define EPSF 1e-6f
#define NBINS 4096
#define TI   8
#define NT   13        // ceil(100/8)
#define NTP  91        // NT*(NT+1)/2
#define FCH  75        // chunks of 256 px covering 138*138 per batch

// ---------------- scratch (static device memory) ----------------
__device__ float    g_key[NB * NP];
__device__ float    g_sconf[NB][TOPK];
__device__ float    g_sloc[NB][TOPK][4];
__device__ float    g_smask[NB][TOPK][NM];
__device__ float    g_ioumax[NB][TOPK];     // atomicMax via positive-float int bits
__device__ float    g_final[NB][PH * PW];
__device__ double   g_acc;
__device__ unsigned g_done;

// ---------------- fast math on FMA pipe ----------------
__device__ __forceinline__ float fexp(float x) {
    x = fminf(fmaxf(x, -87.0f), 88.0f);
    float t = x * 1.4426950408889634f;
    float fi = rintf(t);
    float f = t - fi;
    float p =            1.5403530e-4f;
    p = fmaf(p, f, 1.3333558e-3f);
    p = fmaf(p, f, 9.6181291e-3f);
    p = fmaf(p, f, 5.5504109e-2f);
    p = fmaf(p, f, 2.4022651e-1f);
    p = fmaf(p, f, 6.9314718e-1f);
    p = fmaf(p, f, 1.0f);
    int ei = (int)fi;
    return p * __int_as_float((ei + 127) << 23);
}
__device__ __forceinline__ float frcp(float y) {
    float r = __int_as_float(0x7EF311C3 - __float_as_int(y));
    r = r * (2.0f - y * r);
    r = r * (2.0f - y * r);
    r = r * (2.0f - y * r);
    return r;
}

// ---------------- K1: ordering key per anchor (monotone in conf1) ----------------
__global__ void k_score(const float* __restrict__ conf) {
    int warp = (blockIdx.x * blockDim.x + threadIdx.x) >> 5;
    int lane = threadIdx.x & 31;
    if (warp >= NB * NP) return;
    const float* row = conf + (size_t)warp * NC;
    float v0 = row[lane];
    float v1 = (lane + 32 < NC) ? row[lane + 32] : -INFINITY;
    float v2 = (lane + 64 < NC) ? row[lane + 64] : -INFINITY;
    float m = fmaxf(v0, fmaxf(v1, v2));
    #pragma unroll
    for (int o = 16; o; o >>= 1) m = fmaxf(m, __shfl_xor_sync(0xffffffffu, m, o));
    float s = fexp(v0 - m);
    if (lane + 32 < NC) s += fexp(v1 - m);
    if (lane + 64 < NC) s += fexp(v2 - m);
    #pragma unroll
    for (int o = 16; o; o >>= 1) s += __shfl_xor_sync(0xffffffffu, s, o);
    float c1 = __shfl_sync(0xffffffffu, v0, 1);
    if (lane == 0) g_key[warp] = (c1 - m) * 1.4426950408889634f - __log2f(s);
}

__device__ __forceinline__ unsigned key_bucket(float k) {
    unsigned u = __float_as_uint(k);
    u = (u & 0x80000000u) ? ~u : (u | 0x80000000u);
    unsigned b = u >> 19;
    return b > (NBINS - 1) ? (NBINS - 1) : b;
}

// ---------------- K2: one block per batch: hist -> threshold -> compact ->
//                   exact conf1 recompute -> stable sort -> gather top-100 ----------------
__global__ void k_select(const float* __restrict__ conf,
                         const float* __restrict__ loc,
                         const float* __restrict__ mask) {
    __shared__ unsigned s_hist[NBINS];
    __shared__ unsigned s_chunk[32];
    __shared__ int s_cnt, s_thr;
    __shared__ float s_val[1024];
    __shared__ int   s_idx[1024];
    int b = blockIdx.x, t = threadIdx.x;
    int lane = t & 31, wp = t >> 5;

    for (int i = t; i < NBINS; i += 1024) s_hist[i] = 0;
    if (t == 0) s_cnt = 0;
    __syncthreads();
    cudaGridDependencySynchronize();       // need g_key from k_score
    // pass 1: histogram
    for (int i = t; i < NP; i += 1024)
        atomicAdd(&s_hist[key_bucket(g_key[b * NP + i])], 1u);
    __syncthreads();
    unsigned cs = s_hist[wp * 128 + lane] + s_hist[wp * 128 + lane + 32] +
                  s_hist[wp * 128 + lane + 64] + s_hist[wp * 128 + lane + 96];
    #pragma unroll
    for (int o = 16; o; o >>= 1) cs += __shfl_xor_sync(0xffffffffu, cs, o);
    if (lane == 0) s_chunk[wp] = cs;
    __syncthreads();
    if (t < 32) {
        unsigned suff = s_chunk[t];
        #pragma unroll
        for (int o = 1; o < 32; o <<= 1) {
            unsigned x = __shfl_down_sync(0xffffffffu, suff, o);
            if (t + o < 32) suff += x;
        }
        unsigned sn = __shfl_down_sync(0xffffffffu, suff, 1);
        if (t == 31) sn = 0;
        if (suff >= CAND && sn < CAND) {
            unsigned acc = sn;
            int thr = t * 128;
            for (int bin = t * 128 + 127; bin >= t * 128; --bin) {
                acc += s_hist[bin];
                if (acc >= CAND) { thr = bin; break; }
            }
            s_thr = thr;
        }
    }
    __syncthreads();
    int thr = s_thr;
    for (int i = t; i < NP; i += 1024) {
        if ((int)key_bucket(g_key[b * NP + i]) >= thr) {
            int pos = atomicAdd(&s_cnt, 1);
            if (pos < 1024) s_idx[pos] = i;
        }
    }
    __syncthreads();
    int cnt = s_cnt; if (cnt > 1024) cnt = 1024;
    for (int c = wp; c < cnt; c += 32) {
        const float* row = conf + (size_t)(b * NP + s_idx[c]) * NC;
        float v0 = row[lane];
        float v1 = (lane + 32 < NC) ? row[lane + 32] : -INFINITY;
        float v2 = (lane + 64 < NC) ? row[lane + 64] : -INFINITY;
        float m = fmaxf(v0, fmaxf(v1, v2));
        #pragma unroll
        for (int o = 16; o; o >>= 1) m = fmaxf(m, __shfl_xor_sync(0xffffffffu, m, o));
        float s = expf(v0 - m);
        if (lane + 32 < NC) s += expf(v1 - m);
        if (lane + 64 < NC) s += expf(v2 - m);
        #pragma unroll
        for (int o = 16; o; o >>= 1) s += __shfl_xor_sync(0xffffffffu, s, o);
        float c1 = __shfl_sync(0xffffffffu, v0, 1);
        if (lane == 0) s_val[c] = expf(c1 - m) / s;
    }
    __syncthreads();
    int S = 1; while (S < cnt) S <<= 1;
    if (t >= cnt && t < S) { s_val[t] = -INFINITY; s_idx[t] = 0x7fffffff; }
    __syncthreads();
    // bitonic: (val desc, idx asc) == stable argsort(-conf1)
    for (int k2 = 2; k2 <= S; k2 <<= 1) {
        for (int j = k2 >> 1; j; j >>= 1) {
            if (t < S) {
                int p = t ^ j;
                if (p > t) {
                    float av = s_val[t], bv = s_val[p];
                    int   ai = s_idx[t], bi = s_idx[p];
                    bool tfirst = (av > bv) || (av == bv && ai < bi);
                    bool desc = ((t & k2) == 0);
                    if (desc ? !tfirst : tfirst) {
                        s_val[t] = bv; s_val[p] = av; s_idx[t] = bi; s_idx[p] = ai;
                    }
                }
            }
            __syncthreads();
        }
    }
    if (t < TOPK) {
        int idx = s_idx[t];
        g_sconf[b][t] = s_val[t];
        *(float4*)&g_sloc[b][t][0] = *(const float4*)(loc + (size_t)(b * NP + idx) * 4);
        const float4* mp = (const float4*)(mask + (size_t)(b * NP + idx) * NM);
        float4* dst = (float4*)&g_smask[b][t][0];
        #pragma unroll
        for (int q = 0; q < 8; q++) dst[q] = mp[q];
        g_ioumax[b][t] = 0.f;
    }
    if (b == 0 && t == 0) { g_acc = 0.0; g_done = 0u; }
}

// ---------------- K3: fused gaussian generation + tiled pairwise IoU ----------------
__global__ void k_iou() {
    __shared__ float shB[TI][1024];
    __shared__ float shS[TI];
    int b = blockIdx.x / NTP;
    int q = blockIdx.x % NTP;
    int ti = 0;
    while (q >= NT - ti) { q -= NT - ti; ti++; }
    int tj = ti + q;
    int t = threadIdx.x, wp = t >> 5, l = t & 31;
    float xs = (l + 0.5f) * (1.f / 32.f);
    cudaGridDependencySynchronize();       // need g_sloc/g_ioumax from k_select

    int i = ti * TI + wp;
    int ic = min(i, TOPK - 1);
    float cx = g_sloc[b][ic][0], cy = g_sloc[b][ic][1];
    float sx = fabsf(g_sloc[b][ic][2]) * 0.5f + 0.001f;
    float sy = fabsf(g_sloc[b][ic][3]) * 0.5f + 0.001f;
    float ix = 0.5f * frcp(sx * sx), iy = 0.5f * frcp(sy * sy);
    float dxq = (xs - cx); dxq = dxq * dxq * ix;
    float a[32]; float Si = 0.f;
    #pragma unroll
    for (int r = 0; r < 32; r++) {
        float dy = (r + 0.5f) * (1.f / 32.f) - cy;
        float g = fexp(-fmaf(dy * dy, iy, dxq));
        a[r] = g; Si += g;
    }
    #pragma unroll
    for (int o = 16; o; o >>= 1) Si += __shfl_xor_sync(0xffffffffu, Si, o);

    int j = tj * TI + wp;
    int jc = min(j, TOPK - 1);
    float bx = g_sloc[b][jc][0], by = g_sloc[b][jc][1];
    float bsx = fabsf(g_sloc[b][jc][2]) * 0.5f + 0.001f;
    float bsy = fabsf(g_sloc[b][jc][3]) * 0.5f + 0.001f;
    float bix = 0.5f * frcp(bsx * bsx), biy = 0.5f * frcp(bsy * bsy);
    float bdxq = (xs - bx); bdxq = bdxq * bdxq * bix;
    float Sj = 0.f;
    #pragma unroll
    for (int r = 0; r < 32; r++) {
        float dy = (r + 0.5f) * (1.f / 32.f) - by;
        float g = fexp(-fmaf(dy * dy, biy, bdxq));
        shB[wp][r * 32 + l] = g; Sj += g;
    }
    #pragma unroll
    for (int o = 16; o; o >>= 1) Sj += __shfl_xor_sync(0xffffffffu, Sj, o);
    if (l == 0) shS[wp] = Sj;
    __syncthreads();

    for (int jr = 0; jr < TI; jr++) {
        int jj = tj * TI + jr;
        if (i < jj && jj < TOPK) {
            float D = 0.f;
            #pragma unroll
            for (int r = 0; r < 32; r++) D += fabsf(a[r] - shB[jr][r * 32 + l]);
            #pragma unroll
            for (int o = 16; o; o >>= 1) D += __shfl_xor_sync(0xffffffffu, D, o);
            if (l == 0) {
                float S = Si + shS[jr];
                float iou = (S - D) * frcp(S + D);     // in (0,1): int-bit atomicMax valid
                atomicMax((int*)&g_ioumax[b][jj], __float_as_int(iou));
            }
        }
    }
}

// ---------------- K4: keep-15 (in-block, warp 0) + final_conf per proto pixel ----------------
// two-phase pixel loop: all 15 dots first (60-wide FMA ILP), then all 15 exp terms
__global__ void __launch_bounds__(256) k_final(const float* __restrict__ proto) {
    __shared__ float4 skm4[KEEP][8];
    __shared__ float4 spr[KEEP];      // cx, cy, ix, iy
    __shared__ float  scf[KEEP];
    __shared__ int    skidx[KEEP];
    int bx = blockIdx.x;
    int b = bx / FCH, chunk = bx % FCH;
    int t = threadIdx.x;
    int px = chunk * 256 + t;
    bool valid = (px < PH * PW);

    // proto is a kernel INPUT: load before the PDL sync to overlap with k_iou tail
    float4 pv[8];
    if (valid) {
        const float4* pp = (const float4*)(proto + ((size_t)b * (PH * PW) + px) * NM);
        #pragma unroll
        for (int i2 = 0; i2 < 8; i2++) pv[i2] = pp[i2];
    }
    cudaGridDependencySynchronize();       // need g_ioumax/g_sloc/g_smask

    if (t < 32) {
        // bottom-15 of iou_max, stable ascending (== jnp.argsort)
        float v[4]; int id[4];
        #pragma unroll
        for (int r = 0; r < 4; r++) {
            int ixp = t + 32 * r; id[r] = ixp;
            v[r] = (ixp < TOPK) ? g_ioumax[b][ixp] : INFINITY;
        }
        int mykeep = -1;
        for (int it = 0; it < KEEP; ++it) {
            float bv = INFINITY; int bi = 0x7fffffff;
            #pragma unroll
            for (int r = 0; r < 4; r++)
                if (v[r] < bv || (v[r] == bv && id[r] < bi)) { bv = v[r]; bi = id[r]; }
            #pragma unroll
            for (int o = 16; o; o >>= 1) {
                float ov = __shfl_xor_sync(0xffffffffu, bv, o);
                int   oi = __shfl_xor_sync(0xffffffffu, bi, o);
                if (ov < bv || (ov == bv && oi < bi)) { bv = ov; bi = oi; }
            }
            if (t == it) mykeep = bi;
            #pragma unroll
            for (int r = 0; r < 4; r++) if (id[r] == bi) v[r] = INFINITY;
        }
        if (t < KEEP) {
            int k = mykeep;
            skidx[t] = k;
            float sx = fabsf(g_sloc[b][k][2]) * 0.5f + 0.001f;
            float sy = fabsf(g_sloc[b][k][3]) * 0.5f + 0.001f;
            float4 pr;
            pr.x = g_sloc[b][k][0];
            pr.y = g_sloc[b][k][1];
            pr.z = 0.5f * frcp(sx * sx);
            pr.w = 0.5f * frcp(sy * sy);
            spr[t] = pr;
            scf[t] = g_sconf[b][k];
        }
    }
    __syncthreads();
    for (int i2 = t; i2 < KEEP * 8; i2 += 256) {
        int kk = i2 >> 3, qq = i2 & 7;
        skm4[kk][qq] = *(const float4*)&g_smask[b][skidx[kk]][qq * 4];
    }
    __syncthreads();

    if (!valid) return;
    int h = px / PW, w = px % PW;
    float xs = (w + 0.5f) * (1.f / 138.f), ys = (h + 0.5f) * (1.f / 138.f);

    // phase A: all 15 dot products (independent 4-accumulator chains)
    float dots[KEEP];
    #pragma unroll
    for (int k = 0; k < KEEP; k++) {
        float4 m0 = skm4[k][0], m1 = skm4[k][1], m2 = skm4[k][2], m3 = skm4[k][3];
        float d0 = 0.f, d1 = 0.f, d2 = 0.f, d3 = 0.f;
        d0 = fmaf(pv[0].x, m0.x, d0); d0 = fmaf(pv[0].y, m0.y, d0);
        d0 = fmaf(pv[0].z, m0.z, d0); d0 = fmaf(pv[0].w, m0.w, d0);
        d1 = fmaf(pv[1].x, m1.x, d1); d1 = fmaf(pv[1].y, m1.y, d1);
        d1 = fmaf(pv[1].z, m1.z, d1); d1 = fmaf(pv[1].w, m1.w, d1);
        d2 = fmaf(pv[2].x, m2.x, d2); d2 = fmaf(pv[2].y, m2.y, d2);
        d2 = fmaf(pv[2].z, m2.z, d2); d2 = fmaf(pv[2].w, m2.w, d2);
        d3 = fmaf(pv[3].x, m3.x, d3); d3 = fmaf(pv[3].y, m3.y, d3);
        d3 = fmaf(pv[3].z, m3.z, d3); d3 = fmaf(pv[3].w, m3.w, d3);
        m0 = skm4[k][4]; m1 = skm4[k][5]; m2 = skm4[k][6]; m3 = skm4[k][7];
        d0 = fmaf(pv[4].x, m0.x, d0); d0 = fmaf(pv[4].y, m0.y, d0);
        d0 = fmaf(pv[4].z, m0.z, d0); d0 = fmaf(pv[4].w, m0.w, d0);
        d1 = fmaf(pv[5].x, m1.x, d1); d1 = fmaf(pv[5].y, m1.y, d1);
        d1 = fmaf(pv[5].z, m1.z, d1); d1 = fmaf(pv[5].w, m1.w, d1);
        d2 = fmaf(pv[6].x, m2.x, d2); d2 = fmaf(pv[6].y, m2.y, d2);
        d2 = fmaf(pv[6].z, m2.z, d2); d2 = fmaf(pv[6].w, m2.w, d2);
        d3 = fmaf(pv[7].x, m3.x, d3); d3 = fmaf(pv[7].y, m3.y, d3);
        d3 = fmaf(pv[7].z, m3.z, d3); d3 = fmaf(pv[7].w, m3.w, d3);
        dots[k] = (d0 + d1) + (d2 + d3);
    }

    // phase B: all 15 attention terms (independent exp/rcp chains), accumulate
    float denom = 0.f, num = 0.f;
    #pragma unroll
    for (int k = 0; k < KEEP; k++) {
        float4 pr = spr[k];
        float dx = xs - pr.x, dy = ys - pr.y;
        float sig = frcp(1.f + fexp(-dots[k]));
        float ug = fexp(-(dx * dx * pr.z + dy * dy * pr.w));
        float aa = sig * ug * scf[k];
        denom += aa; num = fmaf(aa, aa, num);
    }
    float f = 1.f - num * frcp(denom + EPSF);
    if (isnan(f)) f = 0.f;
    g_final[b][px] = f;
}

// ---------------- K5: fused bilinear resize + weighted variance; 4 px/thread ----------------
__global__ void k_loss(const float* __restrict__ orig, float* __restrict__ out) {
    __shared__ float red[8];
    int i4 = blockIdx.x * 256 + threadIdx.x;
    bool act = (i4 < NPX / 4);
    int p0 = i4 * 4;
    // orig is a kernel INPUT: load before the PDL sync to overlap with k_final tail
    float4 ov[3][NB];
    if (act) {
        #pragma unroll
        for (int c = 0; c < 3; c++)
            #pragma unroll
            for (int b = 0; b < NB; b++)
                ov[c][b] = *(const float4*)(orig + (size_t)(b * 3 + c) * NPX + p0);
    }
    cudaGridDependencySynchronize();       // need g_final
    float local = 0.f;
    if (act) {
        #pragma unroll
        for (int e = 0; e < 4; e++) {
            int p = p0 + e;
            int hh = p / IW, ww = p % IW;
            float fy = (hh + 0.5f) * (138.f / 550.f) - 0.5f;
            float fx = (ww + 0.5f) * (138.f / 550.f) - 0.5f;
            float y0f = floorf(fy), x0f = floorf(fx);
            float wy = fy - y0f, wx = fx - x0f;
            int y0 = (int)y0f, x0 = (int)x0f;
            int y0c = min(max(y0, 0), PH - 1), y1c = min(max(y0 + 1, 0), PH - 1);
            int x0c = min(max(x0, 0), PW - 1), x1c = min(max(x0 + 1, 0), PW - 1);
            float rb[NB]; float total = 0.f;
            #pragma unroll
            for (int b = 0; b < NB; b++) {
                const float* F = g_final[b];
                float v00 = F[y0c * PW + x0c], v01 = F[y0c * PW + x1c];
                float v10 = F[y1c * PW + x0c], v11 = F[y1c * PW + x1c];
                float v = (1.f - wy) * ((1.f - wx) * v00 + wx * v01)
                        +        wy  * ((1.f - wx) * v10 + wx * v11);
                rb[b] = v; total += v;
            }
            float acc = 0.f;
            #pragma unroll
            for (int c = 0; c < 3; c++) {
                float ob[NB]; float wm = 0.f;
                #pragma unroll
                for (int b = 0; b < NB; b++) {
                    float4 q = ov[c][b];
                    ob[b] = (e == 0) ? q.x : (e == 1) ? q.y : (e == 2) ? q.z : q.w;
                    wm = fmaf(ob[b], rb[b], wm);
                }
                #pragma unroll
                for (int b = 0; b < NB; b++) {
                    float d = ob[b] - wm;
                    acc = fmaf(d * d, rb[b], acc);
                }
            }
            local += acc * frcp(total + EPSF);
        }
    }
    int t = threadIdx.x;
    float s = local;
    #pragma unroll
    for (int o = 16; o; o >>= 1) s += __shfl_xor_sync(0xffffffffu, s, o);
    if ((t & 31) == 0) red[t >> 5] = s;
    __syncthreads();
    if (t == 0) {
        float bs = 0.f;
        #pragma unroll
        for (int q2 = 0; q2 < 8; q2++) bs += red[q2];
        atomicAdd(&g_acc, (double)bs);
        __threadfence();
        unsigned v = atomicAdd(&g_done, 1u);
        if (v == gridDim.x - 1)
            out[0] = (float)(*((volatile double*)&g_acc) * 0.01);
    }
}

// ---------------- launch: 5 graph nodes chained via PDL ----------------
template <typename K, typename... Args>
static inline void launch_pdl(K kernel, dim3 grid, dim3 block, Args... args) {
    cudaLaunchConfig_t cfg = {};
    cfg.gridDim = grid;
    cfg.blockDim = block;
    cfg.dynamicSmemBytes = 0;
    cfg.stream = 0;
    cudaLaunchAttribute attr[1];
    attr[0].id = cudaLaunchAttributeProgrammaticStreamSerialization;
    attr[0].val.programmaticStreamSerializationAllowed = 1;
    cfg.attrs = attr;
    cfg.numAttrs = 1;
    cudaLaunchKernelEx(&cfg, kernel, args...);
}

extern "C" void kernel_launch(void* const* d_in, const int* in_sizes, int n_in,
                              void* d_out, int out_size) {
    const float* orig  = (const float*)d_in[0];
    const float* loc   = (const float*)d_in[1];
    const float* conf  = (const float*)d_in[2];
    const float* mask  = (const float*)d_in[3];
    const float* proto = (const float*)d_in[4];
    float* out = (float*)d_out;

    k_score<<<(NB * NP + 7) / 8, 256>>>(conf);
    launch_pdl(k_select, dim3(NB), dim3(1024), conf, loc, mask);
    launch_pdl(k_iou, dim3(NB * NTP), dim3(256));
    launch_pdl(k_final, dim3(NB * FCH), dim3(256), proto);
    launch_pdl(k_loss, dim3((NPX / 4 + 255) / 256), dim3(256), orig, out);
}